// round 3
// baseline (speedup 1.0000x reference)
#include <cuda_runtime.h>
#include <cuda_bf16.h>

// HebbLinear: blk=1, bsz=256, ind=512, outd=512, all float32.
//   y[b,o]      = bias[o] + sum_i x[b,i]*w[i,o] + sum_i (x[b,i]*alpha[i])*hebb[b,i,o]
//   delta[b,i,o]= x[b,i] * y[b,o]
// d_out layout (concatenated outputs, row-major):
//   [0 : 256*512)                -> out  (blk=1 makes the transpose a layout no-op: y[b,o])
//   [256*512 : +256*512*512)     -> delta[b,i,o]
//
// Strategy: one CTA per sample. Stream hebb[b] (1MB) once with float4 loads,
// reduce to y[b] in smem, then stream delta[b] (1MB) out with float4 stores.
// w is folded into the same loop (L2-resident, 1MB). Memory-bound kernel:
// ~270MB mandatory DRAM traffic.

#define IND  512
#define OUTD 512
#define BSZ  256
#define O4   (OUTD / 4)   // 128 float4 per output row

__global__ __launch_bounds__(512, 2)
void hebb_fused_kernel(const float* __restrict__ x,      // [BSZ, IND]
                       const float* __restrict__ hebb,   // [BSZ, IND, OUTD]
                       const float* __restrict__ w,      // [IND, OUTD]
                       const float* __restrict__ bias,   // [OUTD]
                       const float* __restrict__ alpha,  // [IND]
                       float* __restrict__ out,          // [BSZ, OUTD]
                       float* __restrict__ delta)        // [BSZ, IND, OUTD]
{
    __shared__ float2 xx[IND];        // (x[b,i], x[b,i]*alpha[i])
    __shared__ float4 sred[4][O4];    // cross-isub reduction buffer
    __shared__ float4 sy[O4];         // final y row (as float4)

    const int b    = blockIdx.x;
    const int tid  = threadIdx.x;     // 0..511
    const int o4   = tid & (O4 - 1);  // 0..127  (output float4 index)
    const int isub = tid >> 7;        // 0..3    (i-phase within the stride-4 loop)

    // Load the sample's x row and precompute x*alpha.
    {
        const float xv = x[b * IND + tid];
        xx[tid] = make_float2(xv, xv * alpha[tid]);
    }
    __syncthreads();

    const float4* __restrict__ hb4 =
        reinterpret_cast<const float4*>(hebb) + (size_t)b * (IND * O4);
    const float4* __restrict__ w4 = reinterpret_cast<const float4*>(w);

    // ---- Phase 1: y partials. Each thread owns (o4, isub) and strides i by 4.
    float4 acc = make_float4(0.f, 0.f, 0.f, 0.f);
#pragma unroll 4
    for (int i = isub; i < IND; i += 4) {
        const float2 xv = xx[i];                 // broadcast LDS.64 within warp
        const float4 h  = hb4[i * O4 + o4];      // coalesced LDG.128 (DRAM stream)
        const float4 wv = w4[i * O4 + o4];       // coalesced LDG.128 (L2 hit)
        acc.x = fmaf(xv.y, h.x, fmaf(xv.x, wv.x, acc.x));
        acc.y = fmaf(xv.y, h.y, fmaf(xv.x, wv.y, acc.y));
        acc.z = fmaf(xv.y, h.z, fmaf(xv.x, wv.z, acc.z));
        acc.w = fmaf(xv.y, h.w, fmaf(xv.x, wv.w, acc.w));
    }

    sred[isub][o4] = acc;
    __syncthreads();

    // ---- Reduce 4 partials, add bias, publish y (smem + gmem out).
    if (tid < O4) {
        const float4 a0 = sred[0][tid];
        const float4 a1 = sred[1][tid];
        const float4 a2 = sred[2][tid];
        const float4 a3 = sred[3][tid];
        const float4 bv = reinterpret_cast<const float4*>(bias)[tid];
        float4 yv;
        yv.x = (a0.x + a1.x) + (a2.x + a3.x) + bv.x;
        yv.y = (a0.y + a1.y) + (a2.y + a3.y) + bv.y;
        yv.z = (a0.z + a1.z) + (a2.z + a3.z) + bv.z;
        yv.w = (a0.w + a1.w) + (a2.w + a3.w) + bv.w;
        sy[tid] = yv;
        reinterpret_cast<float4*>(out)[b * O4 + tid] = yv;
    }
    __syncthreads();

    // ---- Phase 2: delta[b,i,o] = x[b,i] * y[b,o]. Pure streaming store.
    float4* __restrict__ d4 =
        reinterpret_cast<float4*>(delta) + (size_t)b * (IND * O4);
    const float4 yv = sy[o4];   // hoisted; broadcast per lane's column group
#pragma unroll 4
    for (int i = isub; i < IND; i += 4) {
        const float xv = xx[i].x;                // broadcast LDS
        float4 v;
        v.x = xv * yv.x;
        v.y = xv * yv.y;
        v.z = xv * yv.z;
        v.w = xv * yv.w;
        d4[i * O4 + o4] = v;                     // coalesced STG.128
    }
}

extern "C" void kernel_launch(void* const* d_in, const int* in_sizes, int n_in,
                              void* d_out, int out_size)
{
    const float* x     = (const float*)d_in[0];  // (1, 256, 512)
    const float* hebb  = (const float*)d_in[1];  // (256, 512, 512)
    const float* w     = (const float*)d_in[2];  // (512, 512)
    const float* bias  = (const float*)d_in[3];  // (512,)
    const float* alpha = (const float*)d_in[4];  // (512,)

    float* out   = (float*)d_out;                // first BSZ*OUTD floats
    float* delta = out + (size_t)BSZ * OUTD;     // remaining BSZ*IND*OUTD floats

    hebb_fused_kernel<<<BSZ, 512>>>(x, hebb, w, bias, alpha, out, delta);
}

// round 5
// speedup vs baseline: 1.0079x; 1.0079x over previous
#include <cuda_runtime.h>
#include <cuda_bf16.h>
#include <cstdint>

// HebbLinear: blk=1, bsz=256, ind=512, outd=512, all float32.
//   y[b,o]      = bias[o] + sum_i x[b,i]*w[i,o] + sum_i (x[b,i]*alpha[i])*hebb[b,i,o]
//   delta[b,i,o]= x[b,i] * y[b,o]
//
// R4: same L2-policy idea as R3, but via createpolicy + ld.global.nc.L2::cache_hint
// (the immediate .L2::evict_* qualifier is illegal on .v4.f32 for sm_103 ptxas).
// w (1MB, reused by all 256 CTAs) pinned evict_last; hebb streamed evict_first;
// delta stores streamed (.cs). Target: DRAM 478MB -> ~275MB.

#define IND  512
#define OUTD 512
#define BSZ  256
#define O4   (OUTD / 4)   // 128 float4 per output row

// ---- L2-policy helpers ----------------------------------------------------
__device__ __forceinline__ uint64_t policy_evict_last() {
    uint64_t p;
    asm("createpolicy.fractional.L2::evict_last.b64 %0, 1.0;" : "=l"(p));
    return p;
}
__device__ __forceinline__ uint64_t policy_evict_first() {
    uint64_t p;
    asm("createpolicy.fractional.L2::evict_first.b64 %0, 1.0;" : "=l"(p));
    return p;
}
__device__ __forceinline__ float4 ldg_hint(const float4* p, uint64_t pol) {
    float4 v;
    asm volatile("ld.global.nc.L2::cache_hint.v4.f32 {%0,%1,%2,%3}, [%4], %5;"
                 : "=f"(v.x), "=f"(v.y), "=f"(v.z), "=f"(v.w)
                 : "l"(p), "l"(pol));
    return v;
}
__device__ __forceinline__ void stg_streaming(float4* p, float4 v) {
    asm volatile("st.global.cs.v4.f32 [%0], {%1,%2,%3,%4};"
                 :: "l"(p), "f"(v.x), "f"(v.y), "f"(v.z), "f"(v.w) : "memory");
}

__global__ __launch_bounds__(512, 2)
void hebb_fused_kernel(const float* __restrict__ x,      // [BSZ, IND]
                       const float* __restrict__ hebb,   // [BSZ, IND, OUTD]
                       const float* __restrict__ w,      // [IND, OUTD]
                       const float* __restrict__ bias,   // [OUTD]
                       const float* __restrict__ alpha,  // [IND]
                       float* __restrict__ out,          // [BSZ, OUTD]
                       float* __restrict__ delta)        // [BSZ, IND, OUTD]
{
    __shared__ float2 xx[IND];        // (x[b,i], x[b,i]*alpha[i])
    __shared__ float4 sred[4][O4];    // cross-isub reduction buffer
    __shared__ float4 sy[O4];         // final y row (as float4)

    const int b    = blockIdx.x;
    const int tid  = threadIdx.x;     // 0..511
    const int o4   = tid & (O4 - 1);  // 0..127  (output float4 index)
    const int isub = tid >> 7;        // 0..3    (i-phase within the stride-4 loop)

    const uint64_t pol_w = policy_evict_last();
    const uint64_t pol_h = policy_evict_first();

    // Load the sample's x row and precompute x*alpha.
    {
        const float xv = x[b * IND + tid];
        xx[tid] = make_float2(xv, xv * alpha[tid]);
    }
    __syncthreads();

    const float4* __restrict__ hb4 =
        reinterpret_cast<const float4*>(hebb) + (size_t)b * (IND * O4);
    const float4* __restrict__ w4 = reinterpret_cast<const float4*>(w);

    // ---- Phase 1: y partials. Each thread owns (o4, isub) and strides i by 4.
    float4 acc = make_float4(0.f, 0.f, 0.f, 0.f);
#pragma unroll 4
    for (int i = isub; i < IND; i += 4) {
        const float2 xv = xx[i];                              // broadcast LDS.64
        const float4 h  = ldg_hint(&hb4[i * O4 + o4], pol_h); // DRAM stream, no L2 claim
        const float4 wv = ldg_hint(&w4 [i * O4 + o4], pol_w); // pinned in L2
        acc.x = fmaf(xv.y, h.x, fmaf(xv.x, wv.x, acc.x));
        acc.y = fmaf(xv.y, h.y, fmaf(xv.x, wv.y, acc.y));
        acc.z = fmaf(xv.y, h.z, fmaf(xv.x, wv.z, acc.z));
        acc.w = fmaf(xv.y, h.w, fmaf(xv.x, wv.w, acc.w));
    }

    sred[isub][o4] = acc;
    __syncthreads();

    // ---- Reduce 4 partials, add bias, publish y (smem + gmem out).
    if (tid < O4) {
        const float4 a0 = sred[0][tid];
        const float4 a1 = sred[1][tid];
        const float4 a2 = sred[2][tid];
        const float4 a3 = sred[3][tid];
        const float4 bv = reinterpret_cast<const float4*>(bias)[tid];
        float4 yv;
        yv.x = (a0.x + a1.x) + (a2.x + a3.x) + bv.x;
        yv.y = (a0.y + a1.y) + (a2.y + a3.y) + bv.y;
        yv.z = (a0.z + a1.z) + (a2.z + a3.z) + bv.z;
        yv.w = (a0.w + a1.w) + (a2.w + a3.w) + bv.w;
        sy[tid] = yv;
        reinterpret_cast<float4*>(out)[b * O4 + tid] = yv;
    }
    __syncthreads();

    // ---- Phase 2: delta[b,i,o] = x[b,i] * y[b,o]. Pure streaming store.
    float4* __restrict__ d4 =
        reinterpret_cast<float4*>(delta) + (size_t)b * (IND * O4);
    const float4 yv = sy[o4];
#pragma unroll 4
    for (int i = isub; i < IND; i += 4) {
        const float xv = xx[i].x;                // broadcast LDS
        float4 v;
        v.x = xv * yv.x;
        v.y = xv * yv.y;
        v.z = xv * yv.z;
        v.w = xv * yv.w;
        stg_streaming(&d4[i * O4 + o4], v);      // coalesced STG.128, streaming
    }
}

extern "C" void kernel_launch(void* const* d_in, const int* in_sizes, int n_in,
                              void* d_out, int out_size)
{
    const float* x     = (const float*)d_in[0];  // (1, 256, 512)
    const float* hebb  = (const float*)d_in[1];  // (256, 512, 512)
    const float* w     = (const float*)d_in[2];  // (512, 512)
    const float* bias  = (const float*)d_in[3];  // (512,)
    const float* alpha = (const float*)d_in[4];  // (512,)

    float* out   = (float*)d_out;                // first BSZ*OUTD floats
    float* delta = out + (size_t)BSZ * OUTD;     // remaining BSZ*IND*OUTD floats

    hebb_fused_kernel<<<BSZ, 512>>>(x, hebb, w, bias, alpha, out, delta);
}